// round 5
// baseline (speedup 1.0000x reference)
#include <cuda_runtime.h>
#include <math.h>

#define NB 16
#define NA 5
#define NH 96
#define NW 96
#define NHW 9216
#define TT 50
#define ROWS 4
#define TPB (ROWS * NW)                 // 384 threads
#define ROWGRP (NH / ROWS)              // 24
#define DENSE_BX (NA * ROWGRP)          // 120 dense blocks per batch
#define N_PART (DENSE_BX * NB)          // 1920

__constant__ float c_aw[NA] = {1.3221f, 3.19275f, 5.05587f, 9.47112f, 11.2364f};
__constant__ float c_ah[NA] = {1.73145f, 4.00944f, 8.09892f, 4.84053f, 10.0071f};

__device__ float4 g_tA[NB * TT];     // gt extents: xlo, xhi, ylo, yhi
__device__ float  g_bz[NB * TT];     // 0.6 * gt area
__device__ float  g_band[NB * TT];   // gh/3 + margin (prune half-band)
__device__ int    g_nv[NB];
__device__ double g_sparse[NB];
__device__ double g_part[N_PART];

__device__ __forceinline__ float sigmoidf_(float x) { return 1.f / (1.f + __expf(-x)); }

// ---------------------------------------------------------------------------
// Kernel 0: per-batch prep + full sparse loss. grid=16, block=64.
// NOTE: no shared-memory double atomics (ATOMS.CAST.SPIN disaster) — the
// per-thread contributions are reduced with warp shuffles.
// ---------------------------------------------------------------------------
__global__ void __launch_bounds__(64)
prep_kernel(const float* __restrict__ out, const float* __restrict__ tgt)
{
    __shared__ float4 sA[TT];
    __shared__ float  sbz[TT];
    __shared__ int    sidx[TT];
    __shared__ int    smask[2];
    __shared__ double wsumd[2];

    const int b = blockIdx.x;
    const int tid = threadIdx.x;

    float xr = 1.f, tcls = 0.f, gx = 0.f, gy = 0.f, gw = 0.f, gh = 0.f, lr = 0.f;
    if (tid < TT) {
        const float* tp = tgt + (b * TT + tid) * 6;
        tcls = tp[0];
        xr = tp[1];
        gx = xr * NW;
        gy = tp[2] * NH;
        gw = tp[3] * NW;
        gh = tp[4] * NH;
        lr = tp[5];
    }
    {
        unsigned m = __ballot_sync(0xffffffffu, xr == 0.f);
        if ((tid & 31) == 0) smask[tid >> 5] = (int)m;
    }
    __syncthreads();
    const int nv = smask[0] ? (__ffs(smask[0]) - 1)
                            : (smask[1] ? 32 + __ffs(smask[1]) - 1 : TT);

    int bn = 0, gi = 0, gj = 0, idx = 0;
    if (tid < TT) {
        const float area = gw * gh;
        float best = -1.f;
#pragma unroll
        for (int k = 0; k < NA; k++) {
            const float inter = fminf(gw, c_aw[k]) * fminf(gh, c_ah[k]);
            const float iou = inter / (area + c_aw[k] * c_ah[k] - inter);
            if (iou > best) { best = iou; bn = k; }
        }
        gi = (int)gx;
        gj = (int)gy;
        idx = bn * NHW + gj * NW + gi;
        sidx[tid] = (tid < nv) ? idx : (-1 - tid);

        const float4 ext = make_float4(gx - 0.5f * gw, gx + 0.5f * gw,
                                       gy - 0.5f * gh, gy + 0.5f * gh);
        sA[tid] = ext;
        sbz[tid] = 0.6f * area;
        g_tA[b * TT + tid] = ext;
        g_bz[b * TT + tid] = 0.6f * area;
        g_band[b * TT + tid] = gh * (1.f / 3.f) + 0.25f;
    }
    if (tid == 0) g_nv[b] = nv;
    __syncthreads();

    bool owner = tid < nv;
    if (owner)
        for (int t2 = tid + 1; t2 < nv; t2++)
            if (sidx[t2] == idx) { owner = false; break; }

    double c = 0.0;
    if (owner) {
        const float* op = out + ((b * NA + bn) * 8) * NHW + gj * NW + gi;
        const float o0 = op[0];
        const float o1 = op[NHW];
        const float o2 = op[2 * NHW];
        const float o3 = op[3 * NHW];
        const float o4 = op[4 * NHW];
        const float o5 = op[5 * NHW];
        const float o6 = op[6 * NHW];
        const float o7 = op[7 * NHW];

        const float x = sigmoidf_(o0);
        const float y = sigmoidf_(o1);
        const float px = x + (float)gi;
        const float py = y + (float)gj;
        const float pw = __expf(o2) * c_aw[bn];
        const float ph = __expf(o3) * c_ah[bn];

        const float tx = gx - (float)gi;
        const float ty = gy - (float)gj;
        const float tw = __logf(gw / c_aw[bn]);
        const float th = __logf(gh / c_ah[bn]);

        const float xlo = px - 0.5f * pw, xhi = px + 0.5f * pw;
        const float ylo = py - 0.5f * ph, yhi = py + 0.5f * ph;

        // tconf = IoU(gt, pred_at)
        const float iw = fminf(gx + 0.5f * gw, xhi) - fmaxf(gx - 0.5f * gw, xlo);
        const float ih = fminf(gy + 0.5f * gh, yhi) - fmaxf(gy - 0.5f * gh, ylo);
        const float ca = (iw > 0.f && ih > 0.f) ? iw * ih : 0.f;
        const float tconf = ca / (gw * gh + pw * ph - ca);

        const float conf = sigmoidf_(o4);

        // full-list over predicate (identical expression to the dense path)
        const float c1 = 0.6f * (pw * ph);
        bool over = false;
        for (int k = 0; k < nv; k++) {
            const float4 a4 = sA[k];
            const float iw2 = fminf(xhi, a4.y) - fmaxf(xlo, a4.x);
            const float ih2 = fminf(yhi, a4.w) - fmaxf(ylo, a4.z);
            if ((fminf(iw2, ih2) > 0.f) &&
                (fmaf(1.6f, iw2 * ih2, -sbz[k]) > c1)) { over = true; break; }
        }

        const float dx = x - tx;   c += 0.5 * (double)(dx * dx);
        const float dy = y - ty;   c += 0.5 * (double)(dy * dy);
        const float dw = o2 - tw;  c += 0.5 * (double)(dw * dw);
        const float dh = o3 - th;  c += 0.5 * (double)(dh * dh);
        const float dc = conf - tconf;
        c += 2.5 * (double)(dc * dc);                 // 0.5 * OBJECT_SCALE
        if (!over) c -= (double)(0.5f * conf * conf); // cancel dense default term

        const float m = fmaxf(o5, o6);
        const float lse = m + __logf(__expf(o5 - m) + __expf(o6 - m));
        c += (double)(lse - (((int)tcls) == 0 ? o5 : o6));

        const float clr = sigmoidf_(o7);
        const float dl = clr - lr;
        c += 0.25 * (double)(dl * dl);
    }

    // warp-shuffle double reduction (deterministic, no atomics)
#pragma unroll
    for (int off = 16; off > 0; off >>= 1)
        c += __shfl_down_sync(0xffffffffu, c, off);
    if ((tid & 31) == 0) wsumd[tid >> 5] = c;
    __syncthreads();
    if (tid == 0) g_sparse[b] = wsumd[0] + wsumd[1];
}

// ---------------------------------------------------------------------------
// Kernel 1: dense no-object term. grid=(120,16), block=384 (4 rows x 1 anchor).
// Coalesced smem fill of precomputed boxes, ballot/popc band-prune compaction,
// plain double store of the block partial (no atomics, no fences).
// ---------------------------------------------------------------------------
__global__ void __launch_bounds__(TPB)
dense_kernel(const float* __restrict__ out)
{
    __shared__ float4 sA[TT + 4];
    __shared__ float  sbz[TT + 4];
    __shared__ int    smask[2];
    __shared__ int    s_nv;
    __shared__ float  wsum[TPB / 32];

    const int b = blockIdx.y;
    const int bx = blockIdx.x;
    const int tid = threadIdx.x;

    const int a = bx / ROWGRP;
    const int j0 = (bx - a * ROWGRP) * ROWS;
    const int jr = tid / NW;
    const int i = tid - jr * NW;
    const int j = j0 + jr;

    // issue output loads early
    const float* op = out + ((b * NA + a) * 8) * NHW + j * NW + i;
    const float o0 = op[0];
    const float o1 = op[NHW];
    const float o2 = op[2 * NHW];
    const float o3 = op[3 * NHW];
    const float o4 = op[4 * NHW];

    if (tid == 0) s_nv = g_nv[b];

    // coalesced load of precomputed boxes + band prune + ballot compaction
    float4 ext; float bz = 0.f;
    bool keep = false;
    if (tid < TT) {
        ext = g_tA[b * TT + tid];
        bz = g_bz[b * TT + tid];
        const float band = g_band[b * TT + tid];
        keep = ((float)j0 < ext.w + band) && ((float)(j0 + ROWS) > ext.z - band);
    }
    __syncthreads();                      // s_nv visible
    if (tid < 64) {
        keep = keep && (tid < s_nv);
        unsigned m = __ballot_sync(0xffffffffu, keep);
        if ((tid & 31) == 0) smask[tid >> 5] = (int)m;
    }
    __syncthreads();
    const unsigned m0 = (unsigned)smask[0];
    const unsigned m1 = (unsigned)smask[1];
    const int cnt = __popc(m0) + __popc(m1);
    if (keep) {
        const unsigned below = (tid < 32) ? (m0 & ((1u << tid) - 1u))
                                          : m1 & ((tid == 32) ? 0u : ((1u << (tid - 32)) - 1u));
        const int pos = ((tid < 32) ? 0 : __popc(m0)) + __popc(below);
        sA[pos] = ext;
        sbz[pos] = bz;
    }
    if (tid < 4) {   // never-firing pad so the chunk-4 loop needs no tail
        sA[cnt + tid] = make_float4(1e30f, -1e30f, 1e30f, -1e30f);
        sbz[cnt + tid] = 0.f;
    }
    __syncthreads();

    const float px = sigmoidf_(o0) + (float)i;
    const float py = sigmoidf_(o1) + (float)j;
    const float pw = __expf(o2) * c_aw[a];
    const float ph = __expf(o3) * c_ah[a];

    const float xlo = px - 0.5f * pw, xhi = px + 0.5f * pw;
    const float ylo = py - 0.5f * ph, yhi = py + 0.5f * ph;
    const float c1 = 0.6f * (pw * ph);

    bool over = false;
    for (int k = 0; k < cnt; k += 4) {
        bool f = false;
#pragma unroll
        for (int u = 0; u < 4; u++) {
            const float4 a4 = sA[k + u];
            const float iw = fminf(xhi, a4.y) - fmaxf(xlo, a4.x);
            const float ih = fminf(yhi, a4.w) - fmaxf(ylo, a4.z);
            f |= (fminf(iw, ih) > 0.f) && (fmaf(1.6f, iw * ih, -sbz[k + u]) > c1);
        }
        if (f) { over = true; break; }
    }

    const float conf = sigmoidf_(o4);
    float term = over ? 0.f : 0.5f * conf * conf;

#pragma unroll
    for (int off = 16; off > 0; off >>= 1)
        term += __shfl_down_sync(0xffffffffu, term, off);
    if ((tid & 31) == 0) wsum[tid >> 5] = term;
    __syncthreads();
    if (tid == 0) {
        float s = 0.f;
#pragma unroll
        for (int k = 0; k < TPB / 32; k++) s += wsum[k];
        g_part[b * DENSE_BX + bx] = (double)s;   // plain store, no atomic
    }
}

// ---------------------------------------------------------------------------
// Kernel 2: sum 1920 partials + 16 sparse sums -> scalar.
// ---------------------------------------------------------------------------
__global__ void __launch_bounds__(256)
finalize_kernel(float* __restrict__ res)
{
    __shared__ double wsumd[8];
    const int tid = threadIdx.x;
    double s = 0.0;
    for (int k = tid; k < N_PART; k += 256) s += g_part[k];
    if (tid < NB) s += g_sparse[tid];
#pragma unroll
    for (int off = 16; off > 0; off >>= 1)
        s += __shfl_down_sync(0xffffffffu, s, off);
    if ((tid & 31) == 0) wsumd[tid >> 5] = s;
    __syncthreads();
    if (tid == 0) {
        double t = 0.0;
#pragma unroll
        for (int k = 0; k < 8; k++) t += wsumd[k];
        res[0] = (float)(t / (double)NB);
    }
}

extern "C" void kernel_launch(void* const* d_in, const int* in_sizes, int n_in,
                              void* d_out, int out_size)
{
    const float* output = (const float*)d_in[0];
    const float* target = (const float*)d_in[1];
    float* res = (float*)d_out;

    prep_kernel<<<NB, 64>>>(output, target);
    dense_kernel<<<dim3(DENSE_BX, NB), TPB>>>(output);
    finalize_kernel<<<1, 256>>>(res);
}

// round 6
// speedup vs baseline: 4.4762x; 4.4762x over previous
#include <cuda_runtime.h>
#include <math.h>

#define NB 16
#define NA 5
#define NH 96
#define NW 96
#define NHW 9216
#define TT 50
#define ROWS 4
#define TPB (ROWS * NW)                 // 384 threads
#define ROWGRP (NH / ROWS)              // 24
#define DENSE_BX (NA * ROWGRP)          // 120 dense blocks per batch
#define N_PART (DENSE_BX * NB)          // 1920

__constant__ float c_aw[NA] = {1.3221f, 3.19275f, 5.05587f, 9.47112f, 11.2364f};
__constant__ float c_ah[NA] = {1.73145f, 4.00944f, 8.09892f, 4.84053f, 10.0071f};

__device__ float4 g_tA[NB * TT];     // gt extents: xlo, xhi, ylo, yhi
__device__ float  g_bz[NB * TT];     // 0.6 * gt area
__device__ float  g_band[NB * TT];   // gh/3 + margin (prune half-band)
__device__ int    g_nv[NB];
__device__ float4 g_m0[NB * TT];     // gx, gy, gw, gh
__device__ float  g_lr[NB * TT];
__device__ int4   g_meta[NB * TT];   // idx(within batch), bn, owner, cls
__device__ double g_sparse[NB];
__device__ double g_part[N_PART];

__device__ __forceinline__ float sigmoidf_(float x) { return 1.f / (1.f + __expf(-x)); }

// ---------------------------------------------------------------------------
// Kernel 0: target parsing, anchor argmax, ownership. ONE block, 800 threads
// (R2-proven layout). No `output` reads, no doubles, no sort.
// ---------------------------------------------------------------------------
__global__ void __launch_bounds__(NB * TT)
box_prep(const float* __restrict__ tgt)
{
    __shared__ int s_nv[NB];
    __shared__ int sidx[NB * TT];

    const int tid = threadIdx.x;      // 0..799
    const int b = tid / TT;
    const int t = tid - b * TT;

    if (tid < NB) s_nv[tid] = TT;
    __syncthreads();

    const float* tp = tgt + tid * 6;
    const float tcls = tp[0];
    const float xr = tp[1];
    const float gx = xr * NW;
    const float gy = tp[2] * NH;
    const float gw = tp[3] * NW;
    const float gh = tp[4] * NH;
    const float lr = tp[5];

    if (xr == 0.f) atomicMin(&s_nv[b], t);   // native int ATOMS

    // best anchor (first-index-wins, matching jnp.argmax)
    const float area = gw * gh;
    int bn = 0;
    float best = -1.f;
#pragma unroll
    for (int k = 0; k < NA; k++) {
        const float inter = fminf(gw, c_aw[k]) * fminf(gh, c_ah[k]);
        const float iou = inter / (area + c_aw[k] * c_ah[k] - inter);
        if (iou > best) { best = iou; bn = k; }
    }
    const int gi = (int)gx;
    const int gj = (int)gy;
    const int idx = bn * NHW + gj * NW + gi;
    sidx[tid] = idx;
    __syncthreads();

    const int nv = s_nv[b];
    const bool valid = t < nv;

    // last-valid-write-wins: owner iff no later valid target hits the same cell
    bool owner = valid;
    if (owner)
        for (int t2 = t + 1; t2 < nv; t2++)
            if (sidx[b * TT + t2] == idx) { owner = false; break; }

    g_tA[tid] = make_float4(gx - 0.5f * gw, gx + 0.5f * gw,
                            gy - 0.5f * gh, gy + 0.5f * gh);
    g_bz[tid] = 0.6f * area;
    g_band[tid] = gh * (1.f / 3.f) + 0.25f;
    g_m0[tid] = make_float4(gx, gy, gw, gh);
    g_lr[tid] = lr;
    g_meta[tid] = make_int4(idx, bn, owner ? 1 : 0, (int)tcls);
    if (t == 0) g_nv[b] = nv;
}

// ---------------------------------------------------------------------------
// Kernel 1: dense no-object term + sparse per-target loss.
// grid = (121, 16), block = 384.
//   blockIdx.x < 120 : dense (4 rows x 1 anchor), band-pruned, plain store
//   blockIdx.x == 120: sparse loss for batch blockIdx.y (hidden under wave)
// ---------------------------------------------------------------------------
__global__ void __launch_bounds__(TPB)
dense_kernel(const float* __restrict__ out)
{
    __shared__ float4 sA[TT + 4];
    __shared__ float  sbz[TT + 4];
    __shared__ int    smask[2];
    __shared__ int    s_nv;
    __shared__ float  wsum[TPB / 32];
    __shared__ double wsumd[TPB / 32];

    const int b = blockIdx.y;
    const int bx = blockIdx.x;
    const int tid = threadIdx.x;

    if (bx == DENSE_BX) {
        // =================== SPARSE PATH ===================
        if (tid == 0) s_nv = g_nv[b];
        if (tid < TT) {
            sA[tid] = g_tA[b * TT + tid];
            sbz[tid] = g_bz[b * TT + tid];
        }
        __syncthreads();
        const int nv = s_nv;

        double c = 0.0;
        if (tid < TT) {
            const int4 meta = g_meta[b * TT + tid];
            if (meta.z) {
                const int idx = meta.x, bn = meta.y, cls = meta.w;
                const int hw = idx - bn * NHW;
                const int gj = hw / NW;
                const int gi = hw - gj * NW;
                const float4 m0 = g_m0[b * TT + tid];
                const float gx = m0.x, gy = m0.y, gw = m0.z, gh = m0.w;
                const float lr = g_lr[b * TT + tid];

                const float* op = out + ((b * NA + bn) * 8) * NHW + hw;
                const float o0 = op[0];
                const float o1 = op[NHW];
                const float o2 = op[2 * NHW];
                const float o3 = op[3 * NHW];
                const float o4 = op[4 * NHW];
                const float o5 = op[5 * NHW];
                const float o6 = op[6 * NHW];
                const float o7 = op[7 * NHW];

                const float x = sigmoidf_(o0);
                const float y = sigmoidf_(o1);
                const float px = x + (float)gi;
                const float py = y + (float)gj;
                const float pw = __expf(o2) * c_aw[bn];
                const float ph = __expf(o3) * c_ah[bn];

                const float tx = gx - (float)gi;
                const float ty = gy - (float)gj;
                const float tw = __logf(gw / c_aw[bn]);
                const float th = __logf(gh / c_ah[bn]);

                const float xlo = px - 0.5f * pw, xhi = px + 0.5f * pw;
                const float ylo = py - 0.5f * ph, yhi = py + 0.5f * ph;

                // tconf = IoU(gt, pred_at)
                const float iw = fminf(gx + 0.5f * gw, xhi) - fmaxf(gx - 0.5f * gw, xlo);
                const float ih = fminf(gy + 0.5f * gh, yhi) - fmaxf(gy - 0.5f * gh, ylo);
                const float ca = (iw > 0.f && ih > 0.f) ? iw * ih : 0.f;
                const float tconf = ca / (gw * gh + pw * ph - ca);

                const float conf = sigmoidf_(o4);

                // full-list over predicate (identical expression to dense path)
                const float c1 = 0.6f * (pw * ph);
                bool over = false;
                for (int k = 0; k < nv; k++) {
                    const float4 a4 = sA[k];
                    const float iw2 = fminf(xhi, a4.y) - fmaxf(xlo, a4.x);
                    const float ih2 = fminf(yhi, a4.w) - fmaxf(ylo, a4.z);
                    if ((fminf(iw2, ih2) > 0.f) &&
                        (fmaf(1.6f, iw2 * ih2, -sbz[k]) > c1)) { over = true; break; }
                }

                const float dx = x - tx;   c += 0.5 * (double)(dx * dx);
                const float dy = y - ty;   c += 0.5 * (double)(dy * dy);
                const float dw = o2 - tw;  c += 0.5 * (double)(dw * dw);
                const float dh = o3 - th;  c += 0.5 * (double)(dh * dh);
                const float dc = conf - tconf;
                c += 2.5 * (double)(dc * dc);                 // 0.5 * OBJECT_SCALE
                if (!over) c -= (double)(0.5f * conf * conf); // cancel dense term

                const float m = fmaxf(o5, o6);
                const float lse = m + __logf(__expf(o5 - m) + __expf(o6 - m));
                c += (double)(lse - (cls == 0 ? o5 : o6));

                const float clr = sigmoidf_(o7);
                const float dl = clr - lr;
                c += 0.25 * (double)(dl * dl);
            }
        }
        // warp-shuffle double reduction, plain smem stores (no f64 atomics)
#pragma unroll
        for (int off = 16; off > 0; off >>= 1)
            c += __shfl_down_sync(0xffffffffu, c, off);
        if ((tid & 31) == 0) wsumd[tid >> 5] = c;
        __syncthreads();
        if (tid == 0) {
            double s = 0.0;
#pragma unroll
            for (int k = 0; k < TPB / 32; k++) s += wsumd[k];
            g_sparse[b] = s;
        }
        return;
    }

    // =================== DENSE PATH (R4, measured ~8-12us) ===================
    const int a = bx / ROWGRP;
    const int j0 = (bx - a * ROWGRP) * ROWS;
    const int jr = tid / NW;
    const int i = tid - jr * NW;
    const int j = j0 + jr;

    // issue output loads early
    const float* op = out + ((b * NA + a) * 8) * NHW + j * NW + i;
    const float o0 = op[0];
    const float o1 = op[NHW];
    const float o2 = op[2 * NHW];
    const float o3 = op[3 * NHW];
    const float o4 = op[4 * NHW];

    if (tid == 0) s_nv = g_nv[b];

    // coalesced load of precomputed boxes + band prune + ballot compaction
    float4 ext; float bz = 0.f;
    bool keep = false;
    if (tid < TT) {
        ext = g_tA[b * TT + tid];
        bz = g_bz[b * TT + tid];
        const float band = g_band[b * TT + tid];
        keep = ((float)j0 < ext.w + band) && ((float)(j0 + ROWS) > ext.z - band);
    }
    __syncthreads();                      // s_nv visible
    if (tid < 64) {
        keep = keep && (tid < s_nv);
        unsigned m = __ballot_sync(0xffffffffu, keep);
        if ((tid & 31) == 0) smask[tid >> 5] = (int)m;
    }
    __syncthreads();
    const unsigned m0 = (unsigned)smask[0];
    const unsigned m1 = (unsigned)smask[1];
    const int cnt = __popc(m0) + __popc(m1);
    if (keep) {
        const unsigned below = (tid < 32) ? (m0 & ((1u << tid) - 1u))
                                          : m1 & ((tid == 32) ? 0u : ((1u << (tid - 32)) - 1u));
        const int pos = ((tid < 32) ? 0 : __popc(m0)) + __popc(below);
        sA[pos] = ext;
        sbz[pos] = bz;
    }
    if (tid < 4) {   // never-firing pad so the chunk-4 loop needs no tail
        sA[cnt + tid] = make_float4(1e30f, -1e30f, 1e30f, -1e30f);
        sbz[cnt + tid] = 0.f;
    }
    __syncthreads();

    const float px = sigmoidf_(o0) + (float)i;
    const float py = sigmoidf_(o1) + (float)j;
    const float pw = __expf(o2) * c_aw[a];
    const float ph = __expf(o3) * c_ah[a];

    const float xlo = px - 0.5f * pw, xhi = px + 0.5f * pw;
    const float ylo = py - 0.5f * ph, yhi = py + 0.5f * ph;
    const float c1 = 0.6f * (pw * ph);

    bool over = false;
    for (int k = 0; k < cnt; k += 4) {
        bool f = false;
#pragma unroll
        for (int u = 0; u < 4; u++) {
            const float4 a4 = sA[k + u];
            const float iw = fminf(xhi, a4.y) - fmaxf(xlo, a4.x);
            const float ih = fminf(yhi, a4.w) - fmaxf(ylo, a4.z);
            f |= (fminf(iw, ih) > 0.f) && (fmaf(1.6f, iw * ih, -sbz[k + u]) > c1);
        }
        if (f) { over = true; break; }
    }

    const float conf = sigmoidf_(o4);
    float term = over ? 0.f : 0.5f * conf * conf;

#pragma unroll
    for (int off = 16; off > 0; off >>= 1)
        term += __shfl_down_sync(0xffffffffu, term, off);
    if ((tid & 31) == 0) wsum[tid >> 5] = term;
    __syncthreads();
    if (tid == 0) {
        float s = 0.f;
#pragma unroll
        for (int k = 0; k < TPB / 32; k++) s += wsum[k];
        g_part[b * DENSE_BX + bx] = (double)s;   // plain store, no atomic
    }
}

// ---------------------------------------------------------------------------
// Kernel 2: sum 1920 partials + 16 sparse sums -> scalar.
// ---------------------------------------------------------------------------
__global__ void __launch_bounds__(256)
finalize_kernel(float* __restrict__ res)
{
    __shared__ double wsumd[8];
    const int tid = threadIdx.x;
    double s = 0.0;
    for (int k = tid; k < N_PART; k += 256) s += g_part[k];
    if (tid < NB) s += g_sparse[tid];
#pragma unroll
    for (int off = 16; off > 0; off >>= 1)
        s += __shfl_down_sync(0xffffffffu, s, off);
    if ((tid & 31) == 0) wsumd[tid >> 5] = s;
    __syncthreads();
    if (tid == 0) {
        double t = 0.0;
#pragma unroll
        for (int k = 0; k < 8; k++) t += wsumd[k];
        res[0] = (float)(t / (double)NB);
    }
}

extern "C" void kernel_launch(void* const* d_in, const int* in_sizes, int n_in,
                              void* d_out, int out_size)
{
    const float* output = (const float*)d_in[0];
    const float* target = (const float*)d_in[1];
    float* res = (float*)d_out;

    box_prep<<<1, NB * TT>>>(target);
    dense_kernel<<<dim3(DENSE_BX + 1, NB), TPB>>>(output);
    finalize_kernel<<<1, 256>>>(res);
}